// round 15
// baseline (speedup 1.0000x reference)
#include <cuda_runtime.h>
#include <cuda_fp16.h>
#include <math.h>
#include <stdint.h>

// Problem constants
#define BATCH 8192
#define SEQ   4
#define CDIM  1024
#define HEADS 16
#define HDIM  64
#define PDIM  4
#define MROWS (BATCH * SEQ)        // 32768
#define QKVC  (3 * CDIM)           // 3072
#define OUT_ELEMS ((size_t)MROWS * CDIM)
#define SEL_ELEMS ((size_t)BATCH * HEADS * HEADS)

// -------- global scratch (allocation-free per harness rules) --------
__device__ __half g_xh [(size_t)MROWS * CDIM];   // x in fp16
__device__ __half g_wqh[(size_t)QKVC * CDIM];    // W_qkv^T fp16 [3072,1024]
__device__ __half g_wph[(size_t)CDIM * CDIM];    // W_proj fp16 [1024,1024]
__device__ __half g_qkv[(size_t)MROWS * QKVC];   // qkv fp16 (GEMM1 out)
__device__ __half g_hoh[(size_t)MROWS * CDIM];   // attention out fp16

// ======================= helpers =======================
__device__ __forceinline__ uint32_t smem_u32(const void* p) {
    return (uint32_t)__cvta_generic_to_shared(p);
}
__device__ __forceinline__ void cp16(uint32_t dst, const void* src) {
    asm volatile("cp.async.cg.shared.global [%0], [%1], 16;" :: "r"(dst), "l"(src));
}
#define CP_COMMIT()  asm volatile("cp.async.commit_group;" ::: "memory")
#define CP_WAIT1()   asm volatile("cp.async.wait_group 1;" ::: "memory")

#define LDSM4(r, a) \
    asm volatile("ldmatrix.sync.aligned.m8n8.x4.shared.b16 {%0,%1,%2,%3}, [%4];" \
        : "=r"((r)[0]), "=r"((r)[1]), "=r"((r)[2]), "=r"((r)[3]) : "r"(a))

#define MMA16816(d, a, b0, b1) \
    asm volatile("mma.sync.aligned.m16n8k16.row.col.f32.f16.f16.f32 " \
        "{%0,%1,%2,%3}, {%4,%5,%6,%7}, {%8,%9}, {%0,%1,%2,%3};" \
        : "+f"((d)[0]), "+f"((d)[1]), "+f"((d)[2]), "+f"((d)[3]) \
        : "r"((a)[0]), "r"((a)[1]), "r"((a)[2]), "r"((a)[3]), "r"(b0), "r"(b1))

// ======================= HMMA fp16 GEMM =======================
// C[M,N] = A[M,K] * B[N,K]^T, A/B fp16 K-major. K % 64 == 0, N % 128 == 0.
// CTA 128x128, BK=64, 3 stages, 128 threads; 4 warps 2x2, 64x64 warp tiles.
// Stage layout: [A ks0 8KB][A ks1 8KB][B ks0 8KB][B ks1 8KB] = 32KB.
// OUTH: write fp16 output (qkv); else f32 (+bias).
#define STAGE_BYTES 32768
#define NSTAGE 3
#define G_SMEM (NSTAGE * STAGE_BYTES)   // 98304

template<bool BIAS, bool OUTH>
__global__ void __launch_bounds__(128, 2) gemm_hmma(
    const __half* __restrict__ A, const __half* __restrict__ B,
    const float* __restrict__ bias, float* __restrict__ Cf,
    __half* __restrict__ Ch, int Mn, int Nn, int Kn)
{
    extern __shared__ __align__(128) char smem[];
    const uint32_t sb = smem_u32(smem);
    const int tid = threadIdx.x;
    const int lane = tid & 31, wid = tid >> 5;
    const int warp_m = wid & 1, warp_n = wid >> 1;     // 2 x 2 warp grid
    const int m0 = blockIdx.y * 128, n0 = blockIdx.x * 128;
    const int KT2 = Kn >> 6;

    const __half* Ag = A + (size_t)m0 * Kn;
    const __half* Bg = B + (size_t)n0 * Kn;

    // per-thread cp.async coords (512 chunks per 32-K subtile, 4/thread)
    int l_row[4], l_c[4]; uint32_t l_sw[4];
    #pragma unroll
    for (int h = 0; h < 4; h++) {
        int id = tid + h * 128;
        l_row[h] = id >> 2; l_c[h] = id & 3;
        l_sw[h] = (uint32_t)(l_row[h] * 64 + ((l_c[h] ^ ((l_row[h] >> 1) & 3)) << 4));
    }

    #define LD_STAGE(s, kt2) do { \
        uint32_t abase_ = sb + (s) * STAGE_BYTES; \
        uint32_t bbase_ = abase_ + 16384; \
        _Pragma("unroll") \
        for (int h = 0; h < 4; h++) { \
            _Pragma("unroll") \
            for (int ks = 0; ks < 2; ks++) { \
                cp16(abase_ + ks * 8192 + l_sw[h], \
                     Ag + (size_t)l_row[h] * Kn + (kt2) * 64 + ks * 32 + l_c[h] * 8); \
                cp16(bbase_ + ks * 8192 + l_sw[h], \
                     Bg + (size_t)l_row[h] * Kn + (kt2) * 64 + ks * 32 + l_c[h] * 8); \
            } \
        } \
    } while (0)

    LD_STAGE(0, 0); CP_COMMIT();
    LD_STAGE(1, 1); CP_COMMIT();

    float acc[4][8][4];
    #pragma unroll
    for (int i = 0; i < 4; i++)
        #pragma unroll
        for (int j = 0; j < 8; j++)
            #pragma unroll
            for (int q = 0; q < 4; q++) acc[i][j][q] = 0.0f;

    const int a_row_l = lane & 15;
    const int a_csel  = lane >> 4;
    const int b_row_l = ((lane >> 4) << 3) + (lane & 7);
    const int b_csel  = (lane >> 3) & 1;

    uint32_t ar[2][4][4], br[2][4][4];

    // load fragments for sub-block kb (= ksub*2 + k16) of given stage into buf
    #define LDFRAG(buf, sbase, kb) do { \
        const int ksub_ = (kb) >> 1, k16_ = (kb) & 1; \
        const uint32_t ab_ = (sbase) + ksub_ * 8192; \
        const uint32_t bb_ = (sbase) + 16384 + ksub_ * 8192; \
        _Pragma("unroll") \
        for (int i = 0; i < 4; i++) { \
            int row = warp_m * 64 + i * 16 + a_row_l; \
            int c = k16_ * 2 + a_csel; \
            LDSM4(ar[buf][i], ab_ + row * 64 + ((c ^ ((row >> 1) & 3)) << 4)); \
        } \
        _Pragma("unroll") \
        for (int j = 0; j < 4; j++) { \
            int row = warp_n * 64 + j * 16 + b_row_l; \
            int c = k16_ * 2 + b_csel; \
            LDSM4(br[buf][j], bb_ + row * 64 + ((c ^ ((row >> 1) & 3)) << 4)); \
        } \
    } while (0)

    int stage = 0;
    for (int kt2 = 0; kt2 < KT2; kt2++) {
        CP_WAIT1();
        __syncthreads();
        if (kt2 + 2 < KT2) {
            int s2 = stage + 2; if (s2 >= NSTAGE) s2 -= NSTAGE;
            LD_STAGE(s2, kt2 + 2);
        }
        CP_COMMIT();

        const uint32_t sbase = sb + stage * STAGE_BYTES;
        LDFRAG(0, sbase, 0);

        #pragma unroll
        for (int kb = 0; kb < 4; kb++) {
            const int cur = kb & 1;
            if (kb < 3) LDFRAG(cur ^ 1, sbase, kb + 1);
            #pragma unroll
            for (int i = 0; i < 4; i++)
                #pragma unroll
                for (int j = 0; j < 8; j++)
                    MMA16816(acc[i][j], ar[cur][i], br[cur][j >> 1][(j & 1) * 2],
                             br[cur][j >> 1][(j & 1) * 2 + 1]);
        }
        if (++stage == NSTAGE) stage = 0;
    }

    // epilogue
    #pragma unroll
    for (int i = 0; i < 4; i++) {
        const int r0 = m0 + warp_m * 64 + i * 16 + (lane >> 2);
        #pragma unroll
        for (int j = 0; j < 8; j++) {
            const int col = n0 + warp_n * 64 + j * 8 + (lane & 3) * 2;
            float2 v0 = make_float2(acc[i][j][0], acc[i][j][1]);
            float2 v1 = make_float2(acc[i][j][2], acc[i][j][3]);
            if (OUTH) {
                *reinterpret_cast<__half2*>(&Ch[(size_t)r0 * Nn + col]) =
                    __floats2half2_rn(v0.x, v0.y);
                *reinterpret_cast<__half2*>(&Ch[(size_t)(r0 + 8) * Nn + col]) =
                    __floats2half2_rn(v1.x, v1.y);
            } else {
                if (BIAS) {
                    float b0v = bias[col], b1v = bias[col + 1];
                    v0.x += b0v; v0.y += b1v; v1.x += b0v; v1.y += b1v;
                }
                *reinterpret_cast<float2*>(&Cf[(size_t)r0 * Nn + col]) = v0;
                *reinterpret_cast<float2*>(&Cf[(size_t)(r0 + 8) * Nn + col]) = v1;
            }
        }
    }
}

// ======================= conversion kernels =======================
__global__ void f2h_k(const float4* __restrict__ in, __half2* __restrict__ out, int n4) {
    int i = blockIdx.x * blockDim.x + threadIdx.x;
    if (i < n4) {
        float4 v = in[i];
        out[2 * i]     = __floats2half2_rn(v.x, v.y);
        out[2 * i + 1] = __floats2half2_rn(v.z, v.w);
    }
}

// in [R, Cc] f32 row-major -> out [Cc, R] fp16 row-major
__global__ void transpose_h_k(const float* __restrict__ in, __half* __restrict__ out,
                              int R, int Cc) {
    __shared__ float t[32][33];
    const int bx = blockIdx.x * 32;
    const int by = blockIdx.y * 32;
    const int tx = threadIdx.x, ty = threadIdx.y;
#pragma unroll
    for (int j = 0; j < 32; j += 8)
        t[ty + j][tx] = in[(size_t)(by + ty + j) * Cc + bx + tx];
    __syncthreads();
#pragma unroll
    for (int j = 0; j < 32; j += 8)
        out[(size_t)(bx + ty + j) * R + by + tx] = __float2half_rn(t[tx][ty + j]);
}

// ======================= per-batch attention kernel =======================
// qkv is fp16 now; math in f32.
__global__ void __launch_bounds__(512) attn_kernel(
    const __half* __restrict__ qkv,
    const float* __restrict__ W_E, const float* __restrict__ W_F,
    __half* __restrict__ ho, float* __restrict__ sel_out)
{
    __shared__ __half s[SEQ * QKVC];  // 24 KB
    const int b = blockIdx.x;
    const int tid = threadIdx.x;

    const float4* src = reinterpret_cast<const float4*>(qkv + (size_t)b * SEQ * QKVC);
    float4* dst = reinterpret_cast<float4*>(s);
#pragma unroll
    for (int i = 0; i < 3; i++) dst[tid + i * 512] = src[tid + i * 512];
    __syncthreads();

    const int h = tid >> 5, lane = tid & 31;
    const __half2* s2 = reinterpret_cast<const __half2*>(s);
    // half2 index bases (per n): q: n*1536 + h*32 + lane ; k: +512 ; v: +1024

    float q[SEQ][2], kk[SEQ][2], vv[SEQ][2];
#pragma unroll
    for (int n = 0; n < SEQ; n++) {
        float2 qf = __half22float2(s2[n * 1536 + h * 32 + lane]);
        float2 kf = __half22float2(s2[n * 1536 + 512 + h * 32 + lane]);
        float2 vf = __half22float2(s2[n * 1536 + 1024 + h * 32 + lane]);
        q[n][0] = qf.x * 0.125f; q[n][1] = qf.y * 0.125f;
        kk[n][0] = kf.x; kk[n][1] = kf.y;
        vv[n][0] = vf.x; vv[n][1] = vf.y;
    }

    float wE[16], wF[16];
#pragma unroll
    for (int i = 0; i < 16; i++) { wE[i] = __ldg(&W_E[i]); wF[i] = __ldg(&W_F[i]); }

    float klow[PDIM][2], vlow[PDIM][2];
#pragma unroll
    for (int p = 0; p < PDIM; p++)
#pragma unroll
        for (int j = 0; j < 2; j++) {
            klow[p][j] = wE[p*4+0]*kk[0][j] + wE[p*4+1]*kk[1][j]
                       + wE[p*4+2]*kk[2][j] + wE[p*4+3]*kk[3][j];
            vlow[p][j] = wF[p*4+0]*vv[0][j] + wF[p*4+1]*vv[1][j]
                       + wF[p*4+2]*vv[2][j] + wF[p*4+3]*vv[3][j];
        }

    float attn[SEQ][PDIM];
#pragma unroll
    for (int n = 0; n < SEQ; n++)
#pragma unroll
        for (int p = 0; p < PDIM; p++) {
            float part = q[n][0]*klow[p][0] + q[n][1]*klow[p][1];
#pragma unroll
            for (int o = 16; o > 0; o >>= 1)
                part += __shfl_xor_sync(0xffffffffu, part, o);
            attn[n][p] = part;
        }

#pragma unroll
    for (int n = 0; n < SEQ; n++) {
        float mx = fmaxf(fmaxf(attn[n][0], attn[n][1]), fmaxf(attn[n][2], attn[n][3]));
        float e0 = expf(attn[n][0]-mx), e1 = expf(attn[n][1]-mx);
        float e2 = expf(attn[n][2]-mx), e3 = expf(attn[n][3]-mx);
        float inv = 1.0f / (e0 + e1 + e2 + e3);
        attn[n][0] = e0*inv; attn[n][1] = e1*inv; attn[n][2] = e2*inv; attn[n][3] = e3*inv;
    }

#pragma unroll
    for (int n = 0; n < SEQ; n++) {
        float o0 = attn[n][0]*vlow[0][0] + attn[n][1]*vlow[1][0]
                 + attn[n][2]*vlow[2][0] + attn[n][3]*vlow[3][0];
        float o1 = attn[n][0]*vlow[0][1] + attn[n][1]*vlow[1][1]
                 + attn[n][2]*vlow[2][1] + attn[n][3]*vlow[3][1];
        *reinterpret_cast<__half2*>(
            &ho[(size_t)(b * SEQ + n) * CDIM + h * HDIM + (lane << 1)]) =
            __floats2half2_rn(o0, o1);
    }

    // sel: q[n=1] . k[n=2, head g]
    float selval = 0.0f;
#pragma unroll
    for (int g = 0; g < HEADS; g++) {
        float2 kg = __half22float2(s2[2 * 1536 + 512 + g * 32 + lane]);
        float part = q[1][0] * kg.x + q[1][1] * kg.y;
#pragma unroll
        for (int o = 16; o > 0; o >>= 1)
            part += __shfl_xor_sync(0xffffffffu, part, o);
        if (lane == g) selval = part;
    }
    if (lane < HEADS)
        sel_out[(size_t)b * HEADS * HEADS + h * HEADS + lane] =
            1.0f / (1.0f + expf(-selval));
}

// ======================= launch =======================
extern "C" void kernel_launch(void* const* d_in, const int* in_sizes, int n_in,
                              void* d_out, int out_size) {
    const float* x      = (const float*)d_in[0];
    const float* W_qkv  = (const float*)d_in[1];
    const float* W_proj = (const float*)d_in[2];
    const float* b_proj = (const float*)d_in[3];
    const float* W_E    = (const float*)d_in[4];
    const float* W_F    = (const float*)d_in[5];
    float* out = (float*)d_out;
    float* sel = out + OUT_ELEMS;

    static __half *xh = nullptr, *wqh = nullptr, *wph = nullptr,
                  *hoh = nullptr, *qkv = nullptr;
    if (!xh) {
        cudaGetSymbolAddress((void**)&xh,  g_xh);
        cudaGetSymbolAddress((void**)&wqh, g_wqh);
        cudaGetSymbolAddress((void**)&wph, g_wph);
        cudaGetSymbolAddress((void**)&hoh, g_hoh);
        cudaGetSymbolAddress((void**)&qkv, g_qkv);
        cudaFuncSetAttribute((const void*)gemm_hmma<false, true>,
            cudaFuncAttributeMaxDynamicSharedMemorySize, G_SMEM);
        cudaFuncSetAttribute((const void*)gemm_hmma<true, false>,
            cudaFuncAttributeMaxDynamicSharedMemorySize, G_SMEM);
    }

    // conversions
    f2h_k<<<(OUT_ELEMS / 4 + 255) / 256, 256>>>(
        (const float4*)x, (__half2*)xh, (int)(OUT_ELEMS / 4));
    transpose_h_k<<<dim3(QKVC / 32, CDIM / 32), dim3(32, 8)>>>(
        W_qkv, wqh, CDIM, QKVC);
    f2h_k<<<(CDIM * CDIM / 4 + 255) / 256, 256>>>(
        (const float4*)W_proj, (__half2*)wph, CDIM * CDIM / 4);

    // 1) qkv = x @ W_qkv  (fp16 output)
    gemm_hmma<false, true><<<dim3(QKVC / 128, MROWS / 128), 128, G_SMEM>>>(
        xh, wqh, nullptr, nullptr, qkv, MROWS, QKVC, CDIM);
    // 2) attention middle + sel gate
    attn_kernel<<<BATCH, 512>>>(qkv, W_E, W_F, hoh, sel);
    // 3) out = ho @ W_proj^T + b_proj  (f32 output + bias)
    gemm_hmma<true, false><<<dim3(CDIM / 128, MROWS / 128), 128, G_SMEM>>>(
        hoh, wph, b_proj, out, nullptr, MROWS, CDIM, CDIM);
}

// round 16
// speedup vs baseline: 1.1267x; 1.1267x over previous
#include <cuda_runtime.h>
#include <cuda_fp16.h>
#include <math.h>
#include <stdint.h>

// Problem constants
#define BATCH 8192
#define SEQ   4
#define CDIM  1024
#define HEADS 16
#define HDIM  64
#define PDIM  4
#define MROWS (BATCH * SEQ)        // 32768
#define QKVC  (3 * CDIM)           // 3072
#define OUT_ELEMS ((size_t)MROWS * CDIM)
#define SEL_ELEMS ((size_t)BATCH * HEADS * HEADS)

// -------- global scratch (allocation-free per harness rules) --------
__device__ __half g_xh [(size_t)MROWS * CDIM];   // x in fp16
__device__ __half g_wqh[(size_t)QKVC * CDIM];    // W_qkv^T fp16 [3072,1024]
__device__ __half g_wph[(size_t)CDIM * CDIM];    // W_proj fp16 [1024,1024]
__device__ __half g_qkv[(size_t)MROWS * QKVC];   // qkv fp16 (GEMM1 out)
__device__ __half g_hoh[(size_t)MROWS * CDIM];   // attention out fp16

// ======================= helpers =======================
__device__ __forceinline__ uint32_t smem_u32(const void* p) {
    return (uint32_t)__cvta_generic_to_shared(p);
}
__device__ __forceinline__ void cp16(uint32_t dst, const void* src) {
    asm volatile("cp.async.cg.shared.global [%0], [%1], 16;" :: "r"(dst), "l"(src));
}
#define CP_COMMIT()  asm volatile("cp.async.commit_group;" ::: "memory")
#define CP_WAIT2()   asm volatile("cp.async.wait_group 2;" ::: "memory")

#define LDSM4(r, a) \
    asm volatile("ldmatrix.sync.aligned.m8n8.x4.shared.b16 {%0,%1,%2,%3}, [%4];" \
        : "=r"((r)[0]), "=r"((r)[1]), "=r"((r)[2]), "=r"((r)[3]) : "r"(a))

#define MMA16816(d, a, b0, b1) \
    asm volatile("mma.sync.aligned.m16n8k16.row.col.f32.f16.f16.f32 " \
        "{%0,%1,%2,%3}, {%4,%5,%6,%7}, {%8,%9}, {%0,%1,%2,%3};" \
        : "+f"((d)[0]), "+f"((d)[1]), "+f"((d)[2]), "+f"((d)[3]) \
        : "r"((a)[0]), "r"((a)[1]), "r"((a)[2]), "r"((a)[3]), "r"(b0), "r"(b1))

// ======================= HMMA fp16 GEMM =======================
// C[M,N] = A[M,K] * B[N,K]^T, A/B fp16 K-major. K % 32 == 0, N % 128 == 0.
// CTA 128x128, BK=32, 6 stages, 128 threads; 4 warps 2x2, 64x64 warp tiles.
// Stage: [A 8KB][B 8KB]. Double-buffered fragments with cross-boundary prefetch:
// wait_group 2 invariant guarantees stage kt+1 complete during iteration kt.
#define STAGE_BYTES 16384
#define NSTAGE 6
#define G_SMEM (NSTAGE * STAGE_BYTES)   // 98304

template<bool BIAS, bool OUTH>
__global__ void __launch_bounds__(128, 2) gemm_hmma(
    const __half* __restrict__ A, const __half* __restrict__ B,
    const float* __restrict__ bias, float* __restrict__ Cf,
    __half* __restrict__ Ch, int Mn, int Nn, int Kn)
{
    extern __shared__ __align__(128) char smem[];
    const uint32_t sb = smem_u32(smem);
    const int tid = threadIdx.x;
    const int lane = tid & 31, wid = tid >> 5;
    const int warp_m = wid & 1, warp_n = wid >> 1;     // 2 x 2 warp grid
    const int m0 = blockIdx.y * 128, n0 = blockIdx.x * 128;
    const int KT = Kn >> 5;

    const __half* Ag = A + (size_t)m0 * Kn;
    const __half* Bg = B + (size_t)n0 * Kn;

    // per-thread cp.async coords: 512 16B chunks per tile, 4/thread for A and B
    int l_row[4], l_c[4]; uint32_t l_sw[4];
    #pragma unroll
    for (int h = 0; h < 4; h++) {
        int id = tid + h * 128;
        l_row[h] = id >> 2; l_c[h] = id & 3;
        l_sw[h] = (uint32_t)(l_row[h] * 64 + ((l_c[h] ^ ((l_row[h] >> 1) & 3)) << 4));
    }

    #define LD_STAGE(s, kt) do { \
        uint32_t abase_ = sb + (s) * STAGE_BYTES; \
        uint32_t bbase_ = abase_ + 8192; \
        _Pragma("unroll") \
        for (int h = 0; h < 4; h++) { \
            cp16(abase_ + l_sw[h], Ag + (size_t)l_row[h] * Kn + (kt) * 32 + l_c[h] * 8); \
            cp16(bbase_ + l_sw[h], Bg + (size_t)l_row[h] * Kn + (kt) * 32 + l_c[h] * 8); \
        } \
    } while (0)

    // prologue: stages 0..3
    LD_STAGE(0, 0); CP_COMMIT();
    LD_STAGE(1, 1); CP_COMMIT();
    LD_STAGE(2, 2); CP_COMMIT();
    LD_STAGE(3, 3); CP_COMMIT();

    float acc[4][8][4];
    #pragma unroll
    for (int i = 0; i < 4; i++)
        #pragma unroll
        for (int j = 0; j < 8; j++)
            #pragma unroll
            for (int q = 0; q < 4; q++) acc[i][j][q] = 0.0f;

    const int a_row_l = lane & 15;
    const int a_csel  = lane >> 4;
    const int b_row_l = ((lane >> 4) << 3) + (lane & 7);
    const int b_csel  = (lane >> 3) & 1;

    uint32_t ar[2][4][4], br[2][4][4];

    // load fragments for sub-block k16 of the stage at sbase into buf
    #define LDFRAG(buf, sbase, k16) do { \
        const uint32_t ab_ = (sbase); \
        const uint32_t bb_ = (sbase) + 8192; \
        _Pragma("unroll") \
        for (int i = 0; i < 4; i++) { \
            int row = warp_m * 64 + i * 16 + a_row_l; \
            int c = (k16) * 2 + a_csel; \
            LDSM4(ar[buf][i], ab_ + row * 64 + ((c ^ ((row >> 1) & 3)) << 4)); \
        } \
        _Pragma("unroll") \
        for (int j = 0; j < 4; j++) { \
            int row = warp_n * 64 + j * 16 + b_row_l; \
            int c = (k16) * 2 + b_csel; \
            LDSM4(br[buf][j], bb_ + row * 64 + ((c ^ ((row >> 1) & 3)) << 4)); \
        } \
    } while (0)

    #define DO_MMA(buf) do { \
        _Pragma("unroll") \
        for (int i = 0; i < 4; i++) \
            _Pragma("unroll") \
            for (int j = 0; j < 8; j++) \
                MMA16816(acc[i][j], ar[buf][i], br[buf][j >> 1][(j & 1) * 2], \
                         br[buf][j >> 1][(j & 1) * 2 + 1]); \
    } while (0)

    CP_WAIT2();          // 4 groups outstanding -> stages 0,1 complete
    __syncthreads();
    LDFRAG(0, sb, 0);    // stage 0, k16=0

    int stage = 0;
    for (int kt = 0; kt < KT; kt++) {
        const uint32_t sbase = sb + stage * STAGE_BYTES;
        int stage_n = stage + 1; if (stage_n == NSTAGE) stage_n = 0;
        const uint32_t sbase_n = sb + stage_n * STAGE_BYTES;

        // kb=0: prefetch k16=1 of current stage into buf1, MMA buf0
        LDFRAG(1, sbase, 1);
        DO_MMA(0);
        // kb=1: cross-boundary prefetch k16=0 of NEXT stage into buf0, MMA buf1
        // (stage kt+1 complete by wait invariant; garbage at kt=KT-1, unused)
        LDFRAG(0, sbase_n, 0);
        DO_MMA(1);

        // issue next stage's loads (off critical path), then advance pipeline
        if (kt + 4 < KT) {
            int s4 = stage + 4; if (s4 >= NSTAGE) s4 -= NSTAGE;
            LD_STAGE(s4, kt + 4);
        }
        CP_COMMIT();
        CP_WAIT2();      // invariant: stages <= kt+2 complete
        __syncthreads();
        stage = stage_n;
    }

    // epilogue
    #pragma unroll
    for (int i = 0; i < 4; i++) {
        const int r0 = m0 + warp_m * 64 + i * 16 + (lane >> 2);
        #pragma unroll
        for (int j = 0; j < 8; j++) {
            const int col = n0 + warp_n * 64 + j * 8 + (lane & 3) * 2;
            float2 v0 = make_float2(acc[i][j][0], acc[i][j][1]);
            float2 v1 = make_float2(acc[i][j][2], acc[i][j][3]);
            if (OUTH) {
                *reinterpret_cast<__half2*>(&Ch[(size_t)r0 * Nn + col]) =
                    __floats2half2_rn(v0.x, v0.y);
                *reinterpret_cast<__half2*>(&Ch[(size_t)(r0 + 8) * Nn + col]) =
                    __floats2half2_rn(v1.x, v1.y);
            } else {
                if (BIAS) {
                    float b0v = bias[col], b1v = bias[col + 1];
                    v0.x += b0v; v0.y += b1v; v1.x += b0v; v1.y += b1v;
                }
                *reinterpret_cast<float2*>(&Cf[(size_t)r0 * Nn + col]) = v0;
                *reinterpret_cast<float2*>(&Cf[(size_t)(r0 + 8) * Nn + col]) = v1;
            }
        }
    }
}

// ======================= conversion kernels =======================
__global__ void f2h_k(const float4* __restrict__ in, __half2* __restrict__ out, int n4) {
    int i = blockIdx.x * blockDim.x + threadIdx.x;
    if (i < n4) {
        float4 v = in[i];
        out[2 * i]     = __floats2half2_rn(v.x, v.y);
        out[2 * i + 1] = __floats2half2_rn(v.z, v.w);
    }
}

// in [R, Cc] f32 row-major -> out [Cc, R] fp16 row-major
__global__ void transpose_h_k(const float* __restrict__ in, __half* __restrict__ out,
                              int R, int Cc) {
    __shared__ float t[32][33];
    const int bx = blockIdx.x * 32;
    const int by = blockIdx.y * 32;
    const int tx = threadIdx.x, ty = threadIdx.y;
#pragma unroll
    for (int j = 0; j < 32; j += 8)
        t[ty + j][tx] = in[(size_t)(by + ty + j) * Cc + bx + tx];
    __syncthreads();
#pragma unroll
    for (int j = 0; j < 32; j += 8)
        out[(size_t)(bx + ty + j) * R + by + tx] = __float2half_rn(t[tx][ty + j]);
}

// ======================= per-batch attention kernel =======================
__global__ void __launch_bounds__(512) attn_kernel(
    const __half* __restrict__ qkv,
    const float* __restrict__ W_E, const float* __restrict__ W_F,
    __half* __restrict__ ho, float* __restrict__ sel_out)
{
    __shared__ __half s[SEQ * QKVC];  // 24 KB
    const int b = blockIdx.x;
    const int tid = threadIdx.x;

    const float4* src = reinterpret_cast<const float4*>(qkv + (size_t)b * SEQ * QKVC);
    float4* dst = reinterpret_cast<float4*>(s);
#pragma unroll
    for (int i = 0; i < 3; i++) dst[tid + i * 512] = src[tid + i * 512];
    __syncthreads();

    const int h = tid >> 5, lane = tid & 31;
    const __half2* s2 = reinterpret_cast<const __half2*>(s);

    float q[SEQ][2], kk[SEQ][2], vv[SEQ][2];
#pragma unroll
    for (int n = 0; n < SEQ; n++) {
        float2 qf = __half22float2(s2[n * 1536 + h * 32 + lane]);
        float2 kf = __half22float2(s2[n * 1536 + 512 + h * 32 + lane]);
        float2 vf = __half22float2(s2[n * 1536 + 1024 + h * 32 + lane]);
        q[n][0] = qf.x * 0.125f; q[n][1] = qf.y * 0.125f;
        kk[n][0] = kf.x; kk[n][1] = kf.y;
        vv[n][0] = vf.x; vv[n][1] = vf.y;
    }

    float wE[16], wF[16];
#pragma unroll
    for (int i = 0; i < 16; i++) { wE[i] = __ldg(&W_E[i]); wF[i] = __ldg(&W_F[i]); }

    float klow[PDIM][2], vlow[PDIM][2];
#pragma unroll
    for (int p = 0; p < PDIM; p++)
#pragma unroll
        for (int j = 0; j < 2; j++) {
            klow[p][j] = wE[p*4+0]*kk[0][j] + wE[p*4+1]*kk[1][j]
                       + wE[p*4+2]*kk[2][j] + wE[p*4+3]*kk[3][j];
            vlow[p][j] = wF[p*4+0]*vv[0][j] + wF[p*4+1]*vv[1][j]
                       + wF[p*4+2]*vv[2][j] + wF[p*4+3]*vv[3][j];
        }

    float attn[SEQ][PDIM];
#pragma unroll
    for (int n = 0; n < SEQ; n++)
#pragma unroll
        for (int p = 0; p < PDIM; p++) {
            float part = q[n][0]*klow[p][0] + q[n][1]*klow[p][1];
#pragma unroll
            for (int o = 16; o > 0; o >>= 1)
                part += __shfl_xor_sync(0xffffffffu, part, o);
            attn[n][p] = part;
        }

#pragma unroll
    for (int n = 0; n < SEQ; n++) {
        float mx = fmaxf(fmaxf(attn[n][0], attn[n][1]), fmaxf(attn[n][2], attn[n][3]));
        float e0 = expf(attn[n][0]-mx), e1 = expf(attn[n][1]-mx);
        float e2 = expf(attn[n][2]-mx), e3 = expf(attn[n][3]-mx);
        float inv = 1.0f / (e0 + e1 + e2 + e3);
        attn[n][0] = e0*inv; attn[n][1] = e1*inv; attn[n][2] = e2*inv; attn[n][3] = e3*inv;
    }

#pragma unroll
    for (int n = 0; n < SEQ; n++) {
        float o0 = attn[n][0]*vlow[0][0] + attn[n][1]*vlow[1][0]
                 + attn[n][2]*vlow[2][0] + attn[n][3]*vlow[3][0];
        float o1 = attn[n][0]*vlow[0][1] + attn[n][1]*vlow[1][1]
                 + attn[n][2]*vlow[2][1] + attn[n][3]*vlow[3][1];
        *reinterpret_cast<__half2*>(
            &ho[(size_t)(b * SEQ + n) * CDIM + h * HDIM + (lane << 1)]) =
            __floats2half2_rn(o0, o1);
    }

    float selval = 0.0f;
#pragma unroll
    for (int g = 0; g < HEADS; g++) {
        float2 kg = __half22float2(s2[2 * 1536 + 512 + g * 32 + lane]);
        float part = q[1][0] * kg.x + q[1][1] * kg.y;
#pragma unroll
        for (int o = 16; o > 0; o >>= 1)
            part += __shfl_xor_sync(0xffffffffu, part, o);
        if (lane == g) selval = part;
    }
    if (lane < HEADS)
        sel_out[(size_t)b * HEADS * HEADS + h * HEADS + lane] =
            1.0f / (1.0f + expf(-selval));
}

// ======================= launch =======================
extern "C" void kernel_launch(void* const* d_in, const int* in_sizes, int n_in,
                              void* d_out, int out_size) {
    const float* x      = (const float*)d_in[0];
    const float* W_qkv  = (const float*)d_in[1];
    const float* W_proj = (const float*)d_in[2];
    const float* b_proj = (const float*)d_in[3];
    const float* W_E    = (const float*)d_in[4];
    const float* W_F    = (const float*)d_in[5];
    float* out = (float*)d_out;
    float* sel = out + OUT_ELEMS;

    static __half *xh = nullptr, *wqh = nullptr, *wph = nullptr,
                  *hoh = nullptr, *qkv = nullptr;
    if (!xh) {
        cudaGetSymbolAddress((void**)&xh,  g_xh);
        cudaGetSymbolAddress((void**)&wqh, g_wqh);
        cudaGetSymbolAddress((void**)&wph, g_wph);
        cudaGetSymbolAddress((void**)&hoh, g_hoh);
        cudaGetSymbolAddress((void**)&qkv, g_qkv);
        cudaFuncSetAttribute((const void*)gemm_hmma<false, true>,
            cudaFuncAttributeMaxDynamicSharedMemorySize, G_SMEM);
        cudaFuncSetAttribute((const void*)gemm_hmma<true, false>,
            cudaFuncAttributeMaxDynamicSharedMemorySize, G_SMEM);
    }

    // conversions
    f2h_k<<<(OUT_ELEMS / 4 + 255) / 256, 256>>>(
        (const float4*)x, (__half2*)xh, (int)(OUT_ELEMS / 4));
    transpose_h_k<<<dim3(QKVC / 32, CDIM / 32), dim3(32, 8)>>>(
        W_qkv, wqh, CDIM, QKVC);
    f2h_k<<<(CDIM * CDIM / 4 + 255) / 256, 256>>>(
        (const float4*)W_proj, (__half2*)wph, CDIM * CDIM / 4);

    // 1) qkv = x @ W_qkv  (fp16 output)
    gemm_hmma<false, true><<<dim3(QKVC / 128, MROWS / 128), 128, G_SMEM>>>(
        xh, wqh, nullptr, nullptr, qkv, MROWS, QKVC, CDIM);
    // 2) attention middle + sel gate
    attn_kernel<<<BATCH, 512>>>(qkv, W_E, W_F, hoh, sel);
    // 3) out = ho @ W_proj^T + b_proj  (f32 output + bias)
    gemm_hmma<true, false><<<dim3(CDIM / 128, MROWS / 128), 128, G_SMEM>>>(
        hoh, wph, b_proj, out, nullptr, MROWS, CDIM, CDIM);
}

// round 17
// speedup vs baseline: 1.2082x; 1.0723x over previous
#include <cuda_runtime.h>
#include <cuda_fp16.h>
#include <math.h>
#include <stdint.h>

// Problem constants
#define BATCH 8192
#define SEQ   4
#define CDIM  1024
#define HEADS 16
#define HDIM  64
#define PDIM  4
#define MROWS (BATCH * SEQ)        // 32768
#define QKVC  (3 * CDIM)           // 3072
#define OUT_ELEMS ((size_t)MROWS * CDIM)
#define SEL_ELEMS ((size_t)BATCH * HEADS * HEADS)

// -------- global scratch (allocation-free per harness rules) --------
__device__ __half g_xh [(size_t)MROWS * CDIM];   // x in fp16
__device__ __half g_wqh[(size_t)QKVC * CDIM];    // W_qkv^T fp16 [3072,1024]
__device__ __half g_wph[(size_t)CDIM * CDIM];    // W_proj fp16 [1024,1024]
__device__ __half g_qkv[(size_t)MROWS * QKVC];   // qkv fp16 (GEMM1 out)
__device__ __half g_hoh[(size_t)MROWS * CDIM];   // attention out fp16

// ======================= helpers =======================
__device__ __forceinline__ uint32_t smem_u32(const void* p) {
    return (uint32_t)__cvta_generic_to_shared(p);
}
__device__ __forceinline__ void cp16(uint32_t dst, const void* src) {
    asm volatile("cp.async.cg.shared.global [%0], [%1], 16;" :: "r"(dst), "l"(src));
}
#define CP_COMMIT()  asm volatile("cp.async.commit_group;" ::: "memory")
#define CP_WAIT2()   asm volatile("cp.async.wait_group 2;" ::: "memory")

#define LDSM4(r, a) \
    asm volatile("ldmatrix.sync.aligned.m8n8.x4.shared.b16 {%0,%1,%2,%3}, [%4];" \
        : "=r"((r)[0]), "=r"((r)[1]), "=r"((r)[2]), "=r"((r)[3]) : "r"(a))

#define MMA16816(d, a, b0, b1) \
    asm volatile("mma.sync.aligned.m16n8k16.row.col.f32.f16.f16.f32 " \
        "{%0,%1,%2,%3}, {%4,%5,%6,%7}, {%8,%9}, {%0,%1,%2,%3};" \
        : "+f"((d)[0]), "+f"((d)[1]), "+f"((d)[2]), "+f"((d)[3]) \
        : "r"((a)[0]), "r"((a)[1]), "r"((a)[2]), "r"((a)[3]), "r"(b0), "r"(b1))

// ======================= HMMA fp16 GEMM =======================
// C[M,N] = A[M,K] * B[N,K]^T, A/B fp16 K-major. K = KT*32 (compile-time).
// CTA 128x128, BK=32, 6 stages, 128 threads; 4 warps 2x2, 64x64 warp tiles.
// Stage: [A 8KB][B 8KB]. Double-buffered fragments + cross-boundary prefetch.
// Steady state fully unrolled in blocks of 6 -> compile-time stage indices.
#define STAGE_BYTES 16384
#define NSTAGE 6
#define G_SMEM (NSTAGE * STAGE_BYTES)   // 98304

template<bool BIAS, bool OUTH, int KT>
__global__ void __launch_bounds__(128, 2) gemm_hmma(
    const __half* __restrict__ A, const __half* __restrict__ B,
    const float* __restrict__ bias, float* __restrict__ Cf,
    __half* __restrict__ Ch, int Mn, int Nn)
{
    const int Kn = KT * 32;
    extern __shared__ __align__(128) char smem[];
    const uint32_t sb = smem_u32(smem);
    const int tid = threadIdx.x;
    const int lane = tid & 31, wid = tid >> 5;
    const int warp_m = wid & 1, warp_n = wid >> 1;     // 2 x 2 warp grid
    const int m0 = blockIdx.y * 128, n0 = blockIdx.x * 128;

    const __half* Ag = A + (size_t)m0 * Kn;
    const __half* Bg = B + (size_t)n0 * Kn;

    // per-thread cp.async coords: 512 16B chunks per tile, 4/thread for A and B
    int l_row[4], l_c[4]; uint32_t l_sw[4];
    #pragma unroll
    for (int h = 0; h < 4; h++) {
        int id = tid + h * 128;
        l_row[h] = id >> 2; l_c[h] = id & 3;
        l_sw[h] = (uint32_t)(l_row[h] * 64 + ((l_c[h] ^ ((l_row[h] >> 1) & 3)) << 4));
    }

    #define LD_STAGE(s, kt) do { \
        uint32_t abase_ = sb + (s) * STAGE_BYTES; \
        uint32_t bbase_ = abase_ + 8192; \
        _Pragma("unroll") \
        for (int h = 0; h < 4; h++) { \
            cp16(abase_ + l_sw[h], Ag + (size_t)l_row[h] * Kn + (kt) * 32 + l_c[h] * 8); \
            cp16(bbase_ + l_sw[h], Bg + (size_t)l_row[h] * Kn + (kt) * 32 + l_c[h] * 8); \
        } \
    } while (0)

    // prologue: stages 0..3
    LD_STAGE(0, 0); CP_COMMIT();
    LD_STAGE(1, 1); CP_COMMIT();
    LD_STAGE(2, 2); CP_COMMIT();
    LD_STAGE(3, 3); CP_COMMIT();

    float acc[4][8][4];
    #pragma unroll
    for (int i = 0; i < 4; i++)
        #pragma unroll
        for (int j = 0; j < 8; j++)
            #pragma unroll
            for (int q = 0; q < 4; q++) acc[i][j][q] = 0.0f;

    const int a_row_l = lane & 15;
    const int a_csel  = lane >> 4;
    const int b_row_l = ((lane >> 4) << 3) + (lane & 7);
    const int b_csel  = (lane >> 3) & 1;

    uint32_t ar[2][4][4], br[2][4][4];

    #define LDFRAG(buf, sbase, k16) do { \
        const uint32_t ab_ = (sbase); \
        const uint32_t bb_ = (sbase) + 8192; \
        _Pragma("unroll") \
        for (int i = 0; i < 4; i++) { \
            int row = warp_m * 64 + i * 16 + a_row_l; \
            int c = (k16) * 2 + a_csel; \
            LDSM4(ar[buf][i], ab_ + row * 64 + ((c ^ ((row >> 1) & 3)) << 4)); \
        } \
        _Pragma("unroll") \
        for (int j = 0; j < 4; j++) { \
            int row = warp_n * 64 + j * 16 + b_row_l; \
            int c = (k16) * 2 + b_csel; \
            LDSM4(br[buf][j], bb_ + row * 64 + ((c ^ ((row >> 1) & 3)) << 4)); \
        } \
    } while (0)

    #define DO_MMA(buf) do { \
        _Pragma("unroll") \
        for (int i = 0; i < 4; i++) \
            _Pragma("unroll") \
            for (int j = 0; j < 8; j++) \
                MMA16816(acc[i][j], ar[buf][i], br[buf][j >> 1][(j & 1) * 2], \
                         br[buf][j >> 1][(j & 1) * 2 + 1]); \
    } while (0)

    // one steady-state step; UC = compile-time stage, KTV = runtime kt
    #define STEP_FULL(UC, KTV) do { \
        const uint32_t sbase_   = sb + (UC) * STAGE_BYTES; \
        const uint32_t sbase_n_ = sb + (((UC) + 1) % NSTAGE) * STAGE_BYTES; \
        LDFRAG(1, sbase_, 1); \
        DO_MMA(0); \
        LDFRAG(0, sbase_n_, 0); \
        DO_MMA(1); \
        if ((KTV) + 4 < KT) LD_STAGE(((UC) + 4) % NSTAGE, (KTV) + 4); \
        CP_COMMIT(); \
        CP_WAIT2(); \
        __syncthreads(); \
    } while (0)

    CP_WAIT2();          // 4 groups outstanding -> stages 0,1 complete
    __syncthreads();
    LDFRAG(0, sb, 0);    // stage 0, k16=0

    static_assert(KT % 2 == 0 && KT >= 8, "KT");
    const int NBLK = (KT - 2) / NSTAGE;          // full unroll-6 blocks
    const int REM0 = NBLK * NSTAGE;              // first remainder kt
    #pragma unroll 1
    for (int blk = 0; blk < NBLK; blk++) {
        const int ktb = blk * NSTAGE;
        STEP_FULL(0, ktb + 0);
        STEP_FULL(1, ktb + 1);
        STEP_FULL(2, ktb + 2);
        STEP_FULL(3, ktb + 3);
        STEP_FULL(4, ktb + 4);
        STEP_FULL(5, ktb + 5);
    }
    // remainder (KT=32, NSTAGE=6 -> REM0=30: stages 0,1)
    {
        // kt = REM0 (stage 0)
        const uint32_t s0 = sb, s1 = sb + STAGE_BYTES;
        LDFRAG(1, s0, 1);
        DO_MMA(0);
        LDFRAG(0, s1, 0);
        DO_MMA(1);
        CP_COMMIT(); CP_WAIT2(); __syncthreads();
        // kt = REM0+1 (stage 1), last: no cross-prefetch
        LDFRAG(1, s1, 1);
        DO_MMA(0);
        DO_MMA(1);
        (void)REM0;
    }

    // epilogue
    #pragma unroll
    for (int i = 0; i < 4; i++) {
        const int r0 = m0 + warp_m * 64 + i * 16 + (lane >> 2);
        #pragma unroll
        for (int j = 0; j < 8; j++) {
            const int col = n0 + warp_n * 64 + j * 8 + (lane & 3) * 2;
            float2 v0 = make_float2(acc[i][j][0], acc[i][j][1]);
            float2 v1 = make_float2(acc[i][j][2], acc[i][j][3]);
            if (OUTH) {
                *reinterpret_cast<__half2*>(&Ch[(size_t)r0 * Nn + col]) =
                    __floats2half2_rn(v0.x, v0.y);
                *reinterpret_cast<__half2*>(&Ch[(size_t)(r0 + 8) * Nn + col]) =
                    __floats2half2_rn(v1.x, v1.y);
            } else {
                if (BIAS) {
                    float b0v = bias[col], b1v = bias[col + 1];
                    v0.x += b0v; v0.y += b1v; v1.x += b0v; v1.y += b1v;
                }
                *reinterpret_cast<float2*>(&Cf[(size_t)r0 * Nn + col]) = v0;
                *reinterpret_cast<float2*>(&Cf[(size_t)(r0 + 8) * Nn + col]) = v1;
            }
        }
    }
}

// ======================= fused preprocessing kernel =======================
// blocks [0, 32768): x f32->f16 ; [32768, 35840): W_qkv transpose+convert ;
// [35840, 36864): W_proj f32->f16. 256 threads/block.
#define NB_X   32768
#define NB_TR  3072    // (3072/32) * (1024/32) = 96*32
#define NB_WP  1024

__global__ void __launch_bounds__(256) prep_k(
    const float* __restrict__ x, __half* __restrict__ xh,
    const float* __restrict__ wq, __half* __restrict__ wqT,
    const float* __restrict__ wp, __half* __restrict__ wph)
{
    __shared__ float tl[32][33];
    const int blk = blockIdx.x, tid = threadIdx.x;
    if (blk < NB_X) {
        size_t i = (size_t)blk * 256 + tid;
        float4 v = reinterpret_cast<const float4*>(x)[i];
        __half2* o = reinterpret_cast<__half2*>(xh);
        o[2 * i]     = __floats2half2_rn(v.x, v.y);
        o[2 * i + 1] = __floats2half2_rn(v.z, v.w);
    } else if (blk < NB_X + NB_TR) {
        const int t = blk - NB_X;
        const int bx = (t % 96) * 32;   // col block in wq [1024, 3072]
        const int by = (t / 96) * 32;   // row block
        const int tx = tid & 31, ty = tid >> 5;  // 32 x 8
        #pragma unroll
        for (int j = 0; j < 32; j += 8)
            tl[ty + j][tx] = wq[(size_t)(by + ty + j) * QKVC + bx + tx];
        __syncthreads();
        #pragma unroll
        for (int j = 0; j < 32; j += 8)
            wqT[(size_t)(bx + ty + j) * CDIM + by + tx] =
                __float2half_rn(tl[tx][ty + j]);
    } else {
        size_t i = (size_t)(blk - NB_X - NB_TR) * 256 + tid;
        float4 v = reinterpret_cast<const float4*>(wp)[i];
        __half2* o = reinterpret_cast<__half2*>(wph);
        o[2 * i]     = __floats2half2_rn(v.x, v.y);
        o[2 * i + 1] = __floats2half2_rn(v.z, v.w);
    }
}

// ======================= per-batch attention kernel =======================
__global__ void __launch_bounds__(512) attn_kernel(
    const __half* __restrict__ qkv,
    const float* __restrict__ W_E, const float* __restrict__ W_F,
    __half* __restrict__ ho, float* __restrict__ sel_out)
{
    __shared__ __half s[SEQ * QKVC];  // 24 KB
    const int b = blockIdx.x;
    const int tid = threadIdx.x;

    const float4* src = reinterpret_cast<const float4*>(qkv + (size_t)b * SEQ * QKVC);
    float4* dst = reinterpret_cast<float4*>(s);
#pragma unroll
    for (int i = 0; i < 3; i++) dst[tid + i * 512] = src[tid + i * 512];
    __syncthreads();

    const int h = tid >> 5, lane = tid & 31;
    const __half2* s2 = reinterpret_cast<const __half2*>(s);

    float q[SEQ][2], kk[SEQ][2], vv[SEQ][2];
#pragma unroll
    for (int n = 0; n < SEQ; n++) {
        float2 qf = __half22float2(s2[n * 1536 + h * 32 + lane]);
        float2 kf = __half22float2(s2[n * 1536 + 512 + h * 32 + lane]);
        float2 vf = __half22float2(s2[n * 1536 + 1024 + h * 32 + lane]);
        q[n][0] = qf.x * 0.125f; q[n][1] = qf.y * 0.125f;
        kk[n][0] = kf.x; kk[n][1] = kf.y;
        vv[n][0] = vf.x; vv[n][1] = vf.y;
    }

    float wE[16], wF[16];
#pragma unroll
    for (int i = 0; i < 16; i++) { wE[i] = __ldg(&W_E[i]); wF[i] = __ldg(&W_F[i]); }

    float klow[PDIM][2], vlow[PDIM][2];
#pragma unroll
    for (int p = 0; p < PDIM; p++)
#pragma unroll
        for (int j = 0; j < 2; j++) {
            klow[p][j] = wE[p*4+0]*kk[0][j] + wE[p*4+1]*kk[1][j]
                       + wE[p*4+2]*kk[2][j] + wE[p*4+3]*kk[3][j];
            vlow[p][j] = wF[p*4+0]*vv[0][j] + wF[p*4+1]*vv[1][j]
                       + wF[p*4+2]*vv[2][j] + wF[p*4+3]*vv[3][j];
        }

    float attn[SEQ][PDIM];
#pragma unroll
    for (int n = 0; n < SEQ; n++)
#pragma unroll
        for (int p = 0; p < PDIM; p++) {
            float part = q[n][0]*klow[p][0] + q[n][1]*klow[p][1];
#pragma unroll
            for (int o = 16; o > 0; o >>= 1)
                part += __shfl_xor_sync(0xffffffffu, part, o);
            attn[n][p] = part;
        }

#pragma unroll
    for (int n = 0; n < SEQ; n++) {
        float mx = fmaxf(fmaxf(attn[n][0], attn[n][1]), fmaxf(attn[n][2], attn[n][3]));
        float e0 = expf(attn[n][0]-mx), e1 = expf(attn[n][1]-mx);
        float e2 = expf(attn[n][2]-mx), e3 = expf(attn[n][3]-mx);
        float inv = 1.0f / (e0 + e1 + e2 + e3);
        attn[n][0] = e0*inv; attn[n][1] = e1*inv; attn[n][2] = e2*inv; attn[n][3] = e3*inv;
    }

#pragma unroll
    for (int n = 0; n < SEQ; n++) {
        float o0 = attn[n][0]*vlow[0][0] + attn[n][1]*vlow[1][0]
                 + attn[n][2]*vlow[2][0] + attn[n][3]*vlow[3][0];
        float o1 = attn[n][0]*vlow[0][1] + attn[n][1]*vlow[1][1]
                 + attn[n][2]*vlow[2][1] + attn[n][3]*vlow[3][1];
        *reinterpret_cast<__half2*>(
            &ho[(size_t)(b * SEQ + n) * CDIM + h * HDIM + (lane << 1)]) =
            __floats2half2_rn(o0, o1);
    }

    float selval = 0.0f;
#pragma unroll
    for (int g = 0; g < HEADS; g++) {
        float2 kg = __half22float2(s2[2 * 1536 + 512 + g * 32 + lane]);
        float part = q[1][0] * kg.x + q[1][1] * kg.y;
#pragma unroll
        for (int o = 16; o > 0; o >>= 1)
            part += __shfl_xor_sync(0xffffffffu, part, o);
        if (lane == g) selval = part;
    }
    if (lane < HEADS)
        sel_out[(size_t)b * HEADS * HEADS + h * HEADS + lane] =
            1.0f / (1.0f + expf(-selval));
}

// ======================= launch =======================
extern "C" void kernel_launch(void* const* d_in, const int* in_sizes, int n_in,
                              void* d_out, int out_size) {
    const float* x      = (const float*)d_in[0];
    const float* W_qkv  = (const float*)d_in[1];
    const float* W_proj = (const float*)d_in[2];
    const float* b_proj = (const float*)d_in[3];
    const float* W_E    = (const float*)d_in[4];
    const float* W_F    = (const float*)d_in[5];
    float* out = (float*)d_out;
    float* sel = out + OUT_ELEMS;

    static __half *xh = nullptr, *wqh = nullptr, *wph = nullptr,
                  *hoh = nullptr, *qkv = nullptr;
    if (!xh) {
        cudaGetSymbolAddress((void**)&xh,  g_xh);
        cudaGetSymbolAddress((void**)&wqh, g_wqh);
        cudaGetSymbolAddress((void**)&wph, g_wph);
        cudaGetSymbolAddress((void**)&hoh, g_hoh);
        cudaGetSymbolAddress((void**)&qkv, g_qkv);
        cudaFuncSetAttribute((const void*)gemm_hmma<false, true, 32>,
            cudaFuncAttributeMaxDynamicSharedMemorySize, G_SMEM);
        cudaFuncSetAttribute((const void*)gemm_hmma<true, false, 32>,
            cudaFuncAttributeMaxDynamicSharedMemorySize, G_SMEM);
    }

    // fused preprocessing (x f2h + W_qkv transpose + W_proj f2h)
    prep_k<<<NB_X + NB_TR + NB_WP, 256>>>(x, xh, W_qkv, wqh, W_proj, wph);

    // 1) qkv = x @ W_qkv  (fp16 output)
    gemm_hmma<false, true, 32><<<dim3(QKVC / 128, MROWS / 128), 128, G_SMEM>>>(
        xh, wqh, nullptr, nullptr, qkv, MROWS, QKVC);
    // 2) attention middle + sel gate
    attn_kernel<<<BATCH, 512>>>(qkv, W_E, W_F, hoh, sel);
    // 3) out = ho @ W_proj^T + b_proj  (f32 output + bias)
    gemm_hmma<true, false, 32><<<dim3(CDIM / 128, MROWS / 128), 128, G_SMEM>>>(
        hoh, wph, b_proj, out, nullptr, MROWS, CDIM);
}